// round 3
// baseline (speedup 1.0000x reference)
#include <cuda_runtime.h>
#include <cuda_bf16.h>
#include <cstdint>

#define N_NEURONS 65536
#define N_BKG     100
#define NSYN      5
#define NNZ       655360
#define SEQ_LEN   500
#define SPIKE_P   0.25f

#define OUT_ROW   (N_NEURONS * NSYN)   // 327680
#define NWORDS    16                   // ceil(500/32)
#define NBITW     (N_BKG * NWORDS)     // 1600
#define NBITW4    (NBITW / 4)          // 400 uint4

// ---------------- device scratch (no allocations allowed) ----------------
__device__ int        g_count[N_NEURONS];
__device__ int        g_offs[N_NEURONS + 1];
__device__ int        g_cursor[N_NEURONS];
__device__ ulonglong2 g_ev4[NNZ];   // {pack(v0,v1), pack(v2,v3)}
__device__ float2     g_ev2[NNZ];   // {v4, col_as_float_bits}
__device__ unsigned   g_bits[NBITW];

// ---------------- prep kernels ----------------
__global__ void k_zero_counts() {
    int i = blockIdx.x * blockDim.x + threadIdx.x;
    if (i < N_NEURONS) g_count[i] = 0;
}

__global__ void k_hist(const int* __restrict__ row_idx) {
    int i = blockIdx.x * blockDim.x + threadIdx.x;
    if (i < NNZ) atomicAdd(&g_count[row_idx[i]], 1);
}

__global__ void k_scan() {
    __shared__ int part[1024];
    int tid = threadIdx.x;
    int base = tid * 64;
    int s = 0;
    #pragma unroll 4
    for (int i = 0; i < 64; i++) s += g_count[base + i];
    part[tid] = s;
    __syncthreads();
    if (tid == 0) {
        int run = 0;
        for (int i = 0; i < 1024; i++) { int t = part[i]; part[i] = run; run += t; }
    }
    __syncthreads();
    int run = part[tid];
    for (int i = 0; i < 64; i++) {
        int c = g_count[base + i];
        g_offs[base + i] = run;
        g_cursor[base + i] = run;
        run += c;
    }
    if (tid == 1023) g_offs[N_NEURONS] = run;
}

__global__ void k_scatter(const float* __restrict__ bw,
                          const float* __restrict__ factors,
                          const int* __restrict__ row_idx,
                          const int* __restrict__ col_idx) {
    int e = blockIdx.x * blockDim.x + threadIdx.x;
    if (e >= NNZ) return;
    int n = row_idx[e];
    int pos = atomicAdd(&g_cursor[n], 1);
    float w = bw[e];
    const float* f = factors + (size_t)e * NSYN;
    float v0 = w * f[0], v1 = w * f[1], v2 = w * f[2], v3 = w * f[3], v4 = w * f[4];
    ulonglong2 p;
    p.x = ((unsigned long long)__float_as_uint(v1) << 32) | __float_as_uint(v0);
    p.y = ((unsigned long long)__float_as_uint(v3) << 32) | __float_as_uint(v2);
    g_ev4[pos] = p;
    g_ev2[pos] = make_float2(v4, __int_as_float(col_idx[e]));
}

__global__ void k_spikebits(const float* __restrict__ noise) {
    int i = blockIdx.x * blockDim.x + threadIdx.x;   // i over 1600
    if (i >= NBITW) return;
    int u = i / NWORDS;
    int wi = i % NWORDS;
    unsigned w = 0;
    #pragma unroll 8
    for (int b = 0; b < 32; b++) {
        int t = wi * 32 + b;
        if (t < SEQ_LEN) {
            if (noise[(size_t)t * N_BKG + u] < SPIKE_P) w |= (1u << b);
        }
    }
    g_bits[u * NWORDS + wi] = w;
}

// ---------------- main kernel ----------------
// CTA: 1024 threads = 32 warps. Warp wn owns neuron n0+wn; lane = t within a
// 32-t group. 4 passes x 4 groups cover 16 groups (512 t, last 12 padded-zero).
// Edges for the CTA's 32 neurons staged in smem (contiguous after sort).
// Spike bitmasks as uint4 -> one LDS.128 (broadcast) per edge per pass.
// Output staged through padded smem for coalesced row stores.
#define ECAP 512

__global__ void __launch_bounds__(1024, 2)
k_main(float* __restrict__ out) {
    __shared__ ulonglong2 sE4[ECAP];
    __shared__ float2     sE2[ECAP];
    __shared__ uint4      sBits4[NBITW4];     // [u*4 + pass]
    __shared__ float      sStage[32 * 161];   // 161 pad -> conflict-free

    int tid  = threadIdx.x;
    int wn   = tid >> 5;
    int lane = tid & 31;
    int n0   = blockIdx.x * 32;

    int base = g_offs[n0];
    int end  = g_offs[n0 + 32];
    int cnt  = min(end - base, ECAP);

    for (int i = tid; i < cnt; i += 1024) {
        sE4[i] = g_ev4[base + i];
        sE2[i] = g_ev2[base + i];
    }
    {
        const uint4* gb4 = reinterpret_cast<const uint4*>(g_bits);
        for (int i = tid; i < NBITW4; i += 1024) sBits4[i] = gb4[i];
    }

    int n  = n0 + wn;
    int e0 = g_offs[n];
    int e1 = g_offs[n + 1];
    unsigned lm = 1u << lane;

    __syncthreads();

    for (int pass = 0; pass < 4; pass++) {
        unsigned long long a01[4] = {0ull, 0ull, 0ull, 0ull};
        unsigned long long a23[4] = {0ull, 0ull, 0ull, 0ull};
        float a4[4] = {0.f, 0.f, 0.f, 0.f};

        for (int e = e0; e < e1; ++e) {
            int l = e - base;
            ulonglong2 v; float2 v2;
            if (l < cnt) { v = sE4[l]; v2 = sE2[l]; }
            else         { v = g_ev4[e]; v2 = g_ev2[e]; }   // rare overflow path
            int u = __float_as_int(v2.y);
            uint4 bw4 = sBits4[u * 4 + pass];               // one LDS.128, broadcast
            unsigned wb[4] = { bw4.x & lm, bw4.y & lm, bw4.z & lm, bw4.w & lm };
            #pragma unroll
            for (int gi = 0; gi < 4; gi++) {
                asm("{.reg .pred p;\n\t"
                    "setp.ne.u32 p, %6, 0;\n\t"
                    "@p add.rn.f32x2 %0, %0, %3;\n\t"
                    "@p add.rn.f32x2 %1, %1, %4;\n\t"
                    "@p add.f32 %2, %2, %5;}\n\t"
                    : "+l"(a01[gi]), "+l"(a23[gi]), "+f"(a4[gi])
                    : "l"(v.x), "l"(v.y), "f"(v2.x), "r"(wb[gi]));
            }
        }

        // stage + coalesced store, one 32-t group at a time
        #pragma unroll
        for (int gi = 0; gi < 4; gi++) {
            int g = pass * 4 + gi;
            __syncthreads();  // stage buffer free
            {
                float f0 = __uint_as_float((unsigned)(a01[gi]));
                float f1 = __uint_as_float((unsigned)(a01[gi] >> 32));
                float f2 = __uint_as_float((unsigned)(a23[gi]));
                float f3 = __uint_as_float((unsigned)(a23[gi] >> 32));
                float* sp = &sStage[lane * 161 + wn * 5];
                sp[0] = f0; sp[1] = f1; sp[2] = f2; sp[3] = f3; sp[4] = a4[gi];
            }
            __syncthreads();
            int t = g * 32 + wn;          // warp wn stores t-row wn of this group
            if (t < SEQ_LEN) {
                float* op = out + (size_t)t * OUT_ROW + (size_t)n0 * 5;
                const float* sp = &sStage[wn * 161];
                #pragma unroll
                for (int k = lane; k < 160; k += 32) op[k] = sp[k];
            }
        }
    }
}

// ---------------- launcher ----------------
extern "C" void kernel_launch(void* const* d_in, const int* in_sizes, int n_in,
                              void* d_out, int out_size) {
    const float* noise   = (const float*)d_in[0];  // (1,500,100)
    const float* bw      = (const float*)d_in[1];  // (NNZ,)
    const float* factors = (const float*)d_in[2];  // (NNZ,5)
    const int*   row_idx = (const int*)d_in[3];    // (NNZ,)
    const int*   col_idx = (const int*)d_in[4];    // (NNZ,)
    float* out = (float*)d_out;

    k_zero_counts<<<(N_NEURONS + 255) / 256, 256>>>();
    k_hist<<<(NNZ + 255) / 256, 256>>>(row_idx);
    k_scan<<<1, 1024>>>();
    k_scatter<<<(NNZ + 255) / 256, 256>>>(bw, factors, row_idx, col_idx);
    k_spikebits<<<(NBITW + 255) / 256, 256>>>(noise);
    k_main<<<N_NEURONS / 32, 1024>>>(out);
}

// round 7
// speedup vs baseline: 2.0123x; 2.0123x over previous
#include <cuda_runtime.h>
#include <cuda_bf16.h>
#include <cstdint>

#define N_NEURONS 65536
#define N_BKG     100
#define NSYN      5
#define NNZ       655360
#define SEQ_LEN   500
#define SPIKE_P   0.25f

#define OUT_ROW   (N_NEURONS * NSYN)   // 327680
#define NWORDS    16                   // ceil(500/32)
#define NBITW     (N_BKG * NWORDS)     // 1600
#define NBITW4    (NBITW / 4)          // 400 uint4

// ---------------- device scratch (no allocations allowed) ----------------
__device__ int        g_count[N_NEURONS];
__device__ int        g_offs[N_NEURONS + 1];
__device__ int        g_cursor[N_NEURONS];
__device__ ulonglong2 g_ev4[NNZ];   // {pack(v0,v1), pack(v2,v3)}
__device__ float2     g_ev2[NNZ];   // {v4, col_as_float_bits}
__device__ unsigned   g_bits[NBITW];

// ---------------- prep kernels ----------------
__global__ void k_zero_counts() {
    int i = blockIdx.x * blockDim.x + threadIdx.x;
    if (i < N_NEURONS) g_count[i] = 0;
}

__global__ void k_hist(const int* __restrict__ row_idx) {
    int i = blockIdx.x * blockDim.x + threadIdx.x;
    if (i < NNZ) atomicAdd(&g_count[row_idx[i]], 1);
}

// Two-level shuffle scan (replaces serial thread-0 loop).
__global__ void k_scan() {
    __shared__ int wsum[32];
    int tid  = threadIdx.x;
    int lane = tid & 31;
    int wid  = tid >> 5;
    int base = tid * 64;

    int s = 0;
    #pragma unroll 4
    for (int i = 0; i < 64; i++) s += g_count[base + i];

    // inclusive warp scan of s
    int v = s;
    #pragma unroll
    for (int d = 1; d < 32; d <<= 1) {
        int t = __shfl_up_sync(0xFFFFFFFFu, v, d);
        if (lane >= d) v += t;
    }
    if (lane == 31) wsum[wid] = v;
    __syncthreads();
    if (wid == 0) {
        int w = wsum[lane];
        #pragma unroll
        for (int d = 1; d < 32; d <<= 1) {
            int t = __shfl_up_sync(0xFFFFFFFFu, w, d);
            if (lane >= d) w += t;
        }
        wsum[lane] = w;   // inclusive warp totals
    }
    __syncthreads();

    int excl = v - s + (wid ? wsum[wid - 1] : 0);   // exclusive prefix for this thread
    int run = excl;
    for (int i = 0; i < 64; i++) {
        int c = g_count[base + i];
        g_offs[base + i] = run;
        g_cursor[base + i] = run;
        run += c;
    }
    if (tid == 1023) g_offs[N_NEURONS] = run;
}

__global__ void k_scatter(const float* __restrict__ bw,
                          const float* __restrict__ factors,
                          const int* __restrict__ row_idx,
                          const int* __restrict__ col_idx) {
    int e = blockIdx.x * blockDim.x + threadIdx.x;
    if (e >= NNZ) return;
    int n = row_idx[e];
    int pos = atomicAdd(&g_cursor[n], 1);
    float w = bw[e];
    const float* f = factors + (size_t)e * NSYN;
    float v0 = w * f[0], v1 = w * f[1], v2 = w * f[2], v3 = w * f[3], v4 = w * f[4];
    ulonglong2 p;
    p.x = ((unsigned long long)__float_as_uint(v1) << 32) | __float_as_uint(v0);
    p.y = ((unsigned long long)__float_as_uint(v3) << 32) | __float_as_uint(v2);
    g_ev4[pos] = p;
    g_ev2[pos] = make_float2(v4, __int_as_float(col_idx[e]));
}

__global__ void k_spikebits(const float* __restrict__ noise) {
    int i = blockIdx.x * blockDim.x + threadIdx.x;   // i over 1600
    if (i >= NBITW) return;
    int u = i / NWORDS;
    int wi = i % NWORDS;
    unsigned w = 0;
    #pragma unroll 8
    for (int b = 0; b < 32; b++) {
        int t = wi * 32 + b;
        if (t < SEQ_LEN) {
            if (noise[(size_t)t * N_BKG + u] < SPIKE_P) w |= (1u << b);
        }
    }
    g_bits[u * NWORDS + wi] = w;
}

// ---------------- main kernel ----------------
// CTA: 1024 threads = 32 warps. Warp wn owns neuron n0+wn; lane = t within a
// 32-t group. 4 passes x 4 groups cover 16 groups (512 t, last 12 padded-zero).
// __launch_bounds__(1024, 1): 64 regs/thread so the ~45-reg live set (20 accum
// regs + edge payload + bitmask words) stays in registers — occ=2's 32-reg cap
// forced accumulator spills to local memory (the R3 941us pathology).
#define ECAP 512

__global__ void __launch_bounds__(1024, 1)
k_main(float* __restrict__ out) {
    __shared__ ulonglong2 sE4[ECAP];
    __shared__ float2     sE2[ECAP];
    __shared__ uint4      sBits4[NBITW4];     // [u*4 + pass]
    __shared__ float      sStage[32 * 161];   // 161 pad -> conflict-free

    int tid  = threadIdx.x;
    int wn   = tid >> 5;
    int lane = tid & 31;
    int n0   = blockIdx.x * 32;

    int base = g_offs[n0];
    int end  = g_offs[n0 + 32];
    int cnt  = min(end - base, ECAP);

    for (int i = tid; i < cnt; i += 1024) {
        sE4[i] = g_ev4[base + i];
        sE2[i] = g_ev2[base + i];
    }
    {
        const uint4* gb4 = reinterpret_cast<const uint4*>(g_bits);
        for (int i = tid; i < NBITW4; i += 1024) sBits4[i] = gb4[i];
    }

    int n  = n0 + wn;
    int e0 = g_offs[n];
    int e1 = g_offs[n + 1];
    unsigned lm = 1u << lane;

    __syncthreads();

    for (int pass = 0; pass < 4; pass++) {
        unsigned long long a01[4] = {0ull, 0ull, 0ull, 0ull};
        unsigned long long a23[4] = {0ull, 0ull, 0ull, 0ull};
        float a4[4] = {0.f, 0.f, 0.f, 0.f};

        for (int e = e0; e < e1; ++e) {
            int l = e - base;
            ulonglong2 v; float2 v2;
            if (l < cnt) { v = sE4[l]; v2 = sE2[l]; }
            else         { v = g_ev4[e]; v2 = g_ev2[e]; }   // rare overflow path
            int u = __float_as_int(v2.y);
            uint4 bw4 = sBits4[u * 4 + pass];               // one LDS.128, broadcast
            unsigned wb[4] = { bw4.x & lm, bw4.y & lm, bw4.z & lm, bw4.w & lm };
            #pragma unroll
            for (int gi = 0; gi < 4; gi++) {
                asm("{.reg .pred p;\n\t"
                    "setp.ne.u32 p, %6, 0;\n\t"
                    "@p add.rn.f32x2 %0, %0, %3;\n\t"
                    "@p add.rn.f32x2 %1, %1, %4;\n\t"
                    "@p add.f32 %2, %2, %5;}\n\t"
                    : "+l"(a01[gi]), "+l"(a23[gi]), "+f"(a4[gi])
                    : "l"(v.x), "l"(v.y), "f"(v2.x), "r"(wb[gi]));
            }
        }

        // stage + coalesced store, one 32-t group at a time
        #pragma unroll
        for (int gi = 0; gi < 4; gi++) {
            int g = pass * 4 + gi;
            __syncthreads();  // stage buffer free
            {
                float f0 = __uint_as_float((unsigned)(a01[gi]));
                float f1 = __uint_as_float((unsigned)(a01[gi] >> 32));
                float f2 = __uint_as_float((unsigned)(a23[gi]));
                float f3 = __uint_as_float((unsigned)(a23[gi] >> 32));
                float* sp = &sStage[lane * 161 + wn * 5];
                sp[0] = f0; sp[1] = f1; sp[2] = f2; sp[3] = f3; sp[4] = a4[gi];
            }
            __syncthreads();
            int t = g * 32 + wn;          // warp wn stores t-row wn of this group
            if (t < SEQ_LEN) {
                float* op = out + (size_t)t * OUT_ROW + (size_t)n0 * 5;
                const float* sp = &sStage[wn * 161];
                #pragma unroll
                for (int k = lane; k < 160; k += 32) op[k] = sp[k];
            }
        }
    }
}

// ---------------- launcher ----------------
extern "C" void kernel_launch(void* const* d_in, const int* in_sizes, int n_in,
                              void* d_out, int out_size) {
    const float* noise   = (const float*)d_in[0];  // (1,500,100)
    const float* bw      = (const float*)d_in[1];  // (NNZ,)
    const float* factors = (const float*)d_in[2];  // (NNZ,5)
    const int*   row_idx = (const int*)d_in[3];    // (NNZ,)
    const int*   col_idx = (const int*)d_in[4];    // (NNZ,)
    float* out = (float*)d_out;

    k_zero_counts<<<(N_NEURONS + 255) / 256, 256>>>();
    k_hist<<<(NNZ + 255) / 256, 256>>>(row_idx);
    k_scan<<<1, 1024>>>();
    k_scatter<<<(NNZ + 255) / 256, 256>>>(bw, factors, row_idx, col_idx);
    k_spikebits<<<(NBITW + 255) / 256, 256>>>(noise);
    k_main<<<N_NEURONS / 32, 1024>>>(out);
}